// round 17
// baseline (speedup 1.0000x reference)
#include <cuda_runtime.h>
#include <mma.h>
#include <cuda_fp16.h>
#include <cstddef>
#include <cstdint>

using namespace nvcuda;

#define NN 100000
#define NN_PAD 100096            // 782 * 128
#define NE 1600000
#define SCAN_B 1024
#define NBLK ((NN + SCAN_B - 1) / SCAN_B)   // 98

// ---------------- scratch ---------------------------------------------------
__device__ __half g_x[(size_t)NN_PAD * 128];   // x in fp16 (padded, zeroed)
__device__ __half g_yh[(size_t)NN_PAD * 128];  // y fp16 (gathered over edges)
__device__ __half g_zh[(size_t)NN_PAD * 128];  // z fp16 (streamed per node)
__device__ __half g_h[(size_t)NN_PAD * 128];   // activations fp16 (padded)
__device__ __half g_wcat[3][256 * 128];        // fp16 [Wl ; Wr] per layer
__device__ int    g_cnt[NN];
__device__ int    g_offs[NN + 1];
__device__ int    g_cursor[NN];
__device__ int    g_csrc[NE];
__device__ int    g_bsum[NBLK];

// ---------------- helpers ---------------------------------------------------
__device__ __forceinline__ uint4 pack8h(float4 f0, float4 f1) {
    union { uint4 u; __half2 h[4]; } P;
    P.h[0] = __floats2half2_rn(f0.x, f0.y);
    P.h[1] = __floats2half2_rn(f0.z, f0.w);
    P.h[2] = __floats2half2_rn(f1.x, f1.y);
    P.h[3] = __floats2half2_rn(f1.z, f1.w);
    return P.u;
}
__device__ __forceinline__ uint32_t smem_u32(const void* p) {
    return (uint32_t)__cvta_generic_to_shared(p);
}
#define CPA(dst, src) \
    asm volatile("cp.async.cg.shared.global [%0], [%1], 16;" :: "r"(dst), "l"(src))
#define CPC() asm volatile("cp.async.commit_group;")
#define CPW(n) asm volatile("cp.async.wait_group %0;" :: "n"(n))

// ---------------- CSR build -------------------------------------------------
__global__ void count_deg(const int* __restrict__ dst, int* __restrict__ cnt) {
    int e = blockIdx.x * blockDim.x + threadIdx.x;
    if (e < NE) atomicAdd(cnt + dst[e], 1);
}
__global__ void zero_cnt(int* __restrict__ cnt) {
    int i = blockIdx.x * blockDim.x + threadIdx.x;
    if (i < NN) cnt[i] = 0;
}
__global__ void scan_a(const int* __restrict__ cnt, int* __restrict__ offs,
                       int* __restrict__ bsum) {
    __shared__ int sh[SCAN_B];
    int gid = blockIdx.x * SCAN_B + threadIdx.x;
    int v = (gid < NN) ? cnt[gid] : 0;
    sh[threadIdx.x] = v;
    __syncthreads();
    for (int d = 1; d < SCAN_B; d <<= 1) {
        int t = (threadIdx.x >= d) ? sh[threadIdx.x - d] : 0;
        __syncthreads();
        sh[threadIdx.x] += t;
        __syncthreads();
    }
    if (gid < NN) offs[gid] = sh[threadIdx.x] - v;
    if (threadIdx.x == SCAN_B - 1) bsum[blockIdx.x] = sh[threadIdx.x];
}
__global__ void scan_b(int* __restrict__ bsum) {
    __shared__ int sh[128];
    int v = (threadIdx.x < NBLK) ? bsum[threadIdx.x] : 0;
    sh[threadIdx.x] = v;
    __syncthreads();
    for (int d = 1; d < 128; d <<= 1) {
        int t = (threadIdx.x >= d) ? sh[threadIdx.x - d] : 0;
        __syncthreads();
        sh[threadIdx.x] += t;
        __syncthreads();
    }
    if (threadIdx.x < NBLK) bsum[threadIdx.x] = sh[threadIdx.x] - v;
}
__global__ void scan_c(int* __restrict__ offs, const int* __restrict__ bsum,
                       int* __restrict__ cursor) {
    int gid = blockIdx.x * blockDim.x + threadIdx.x;
    if (gid < NN) {
        int o = offs[gid] + bsum[gid >> 10];
        offs[gid] = o;
        cursor[gid] = o;
    }
    if (gid == 0) offs[NN] = NE;
}
__global__ void place_edges(const int* __restrict__ src, const int* __restrict__ dst,
                            int* __restrict__ cursor, int* __restrict__ csrc) {
    int e = blockIdx.x * blockDim.x + threadIdx.x;
    if (e < NE) {
        int p = atomicAdd(cursor + dst[e], 1);
        csrc[p] = src[e];
    }
}

// ---------------- fp16 conversions -------------------------------------------
__global__ void cvt_x_h(const float4* __restrict__ in, uint4* __restrict__ out) {
    int i = blockIdx.x * blockDim.x + threadIdx.x;
    if (i >= NN_PAD * 16) return;
    uint4 u = make_uint4(0u, 0u, 0u, 0u);
    if (i < NN * 16) u = pack8h(in[2 * i], in[2 * i + 1]);
    out[i] = u;
}
__global__ void cvt_w_h(const float4* __restrict__ Wl, const float4* __restrict__ Wr,
                        uint4* __restrict__ out, int n8half) {
    int i = blockIdx.x * blockDim.x + threadIdx.x;
    if (i < n8half)
        out[i] = pack8h(Wl[2 * i], Wl[2 * i + 1]);
    else if (i < 2 * n8half) {
        int j = i - n8half;
        out[i] = pack8h(Wr[2 * j], Wr[2 * j + 1]);
    }
}

#define LDTH 24
#define STGW 132        // staging row stride in floats
#define ASTG 3072       // A stage bytes: 64 * 24 halves * 2
#define BSTG 6144       // B stage bytes: 128 * 24 halves * 2

// ---------------- FP16 GEMM, 4-warp CTAs, fp16 Y/Z outputs -------------------
// Block tile 64(M) x 128(Ncols), K=128, 2-stage cp.async (proven pattern),
// 4 warps (wm x wn = 2x2), warp tile 32x64. 4 CTAs/SM -> 4 independent
// barrier domains per SM (vs 2 of 8 warps) for better stall overlap.
// Epilogue: 4 passes of 16 rows through smem staging, coalesced fp16 pack;
// each 8-col group routes to YH or ZH by global column (proven R15 pattern).
__global__ __launch_bounds__(128, 4) void h16gemm_hh(
    const __half* __restrict__ A, const __half* __restrict__ B,
    __half* __restrict__ YH, __half* __restrict__ ZH, int N) {
    __shared__ __align__(16) char smraw[2 * ASTG + 2 * BSTG];   // 18432 B
    __half (*As)[64][LDTH]  = reinterpret_cast<__half(*)[64][LDTH]>(smraw);
    __half (*Bs)[128][LDTH] = reinterpret_cast<__half(*)[128][LDTH]>(smraw + 2 * ASTG);
    float* stg = reinterpret_cast<float*>(smraw);   // 16*132*4 = 8448 B reuse

    const int tid = threadIdx.x;
    const int warp = tid >> 5;
    const int wm = warp & 1;      // m offset 32*wm
    const int wn = warp >> 1;     // n offset 64*wn
    const int bm0 = blockIdx.y * 64;
    const int bn0 = blockIdx.x * 128;

    wmma::fragment<wmma::accumulator, 16, 16, 16, float> acc[2][4];
    #pragma unroll
    for (int i = 0; i < 2; i++)
        #pragma unroll
        for (int j = 0; j < 4; j++)
            wmma::fill_fragment(acc[i][j], 0.0f);

    // Loaders per stage: A 64 rows x 16 halves (1 cp.async/thread),
    //                    B 128 rows x 16 halves (2 cp.async/thread, same row).
    const int rA = tid >> 1;
    const int cA = (tid & 1) * 8;
    const __half* Ap = A + (size_t)(bm0 + rA) * 128 + cA;
    const __half* Bp = B + (size_t)(bn0 + tid) * 128;
    const uint32_t sA  = smem_u32(&As[0][rA][cA]);
    const uint32_t sB0 = smem_u32(&Bs[0][tid][0]);
    const uint32_t sB1 = smem_u32(&Bs[0][tid][8]);

    CPA(sA, Ap); CPA(sB0, Bp); CPA(sB1, Bp + 8); CPC();

    #pragma unroll
    for (int t = 0; t < 8; t++) {
        const int cur = t & 1;
        if (t < 7) {
            const int nxt = (t + 1) & 1;
            const int k0 = (t + 1) * 16;
            CPA(sA + nxt * ASTG, Ap + k0);
            CPA(sB0 + nxt * BSTG, Bp + k0);
            CPA(sB1 + nxt * BSTG, Bp + k0 + 8);
            CPC();
            CPW(1);
        } else {
            CPW(0);
        }
        __syncthreads();

        wmma::fragment<wmma::matrix_a, 16, 16, 16, __half, wmma::row_major> af[2];
        wmma::fragment<wmma::matrix_b, 16, 16, 16, __half, wmma::col_major> bf[4];
        wmma::load_matrix_sync(af[0], &As[cur][wm * 32 + 0][0], LDTH);
        wmma::load_matrix_sync(af[1], &As[cur][wm * 32 + 16][0], LDTH);
        #pragma unroll
        for (int j = 0; j < 4; j++)
            wmma::load_matrix_sync(bf[j], &Bs[cur][wn * 64 + j * 16][0], LDTH);
        #pragma unroll
        for (int i = 0; i < 2; i++)
            #pragma unroll
            for (int j = 0; j < 4; j++)
                wmma::mma_sync(acc[i][j], af[i], bf[j], acc[i][j]);

        __syncthreads();   // protect stage 'cur' before iter t+1 overwrites it
    }

    // ---- epilogue: 4 passes of 16 rows; staging + coalesced fp16 pack ----
    const int halfN = N >> 1;
    #pragma unroll
    for (int p = 0; p < 4; p++) {
        if (wm == (p >> 1)) {
            const int i = p & 1;
            #pragma unroll
            for (int j = 0; j < 4; j++)
                wmma::store_matrix_sync(stg + wn * 64 + j * 16, acc[i][j],
                                        STGW, wmma::mem_row_major);
        }
        __syncthreads();
        #pragma unroll
        for (int k = 0; k < 2; k++) {
            int idx = tid + k * 128;           // 256 uint4 total (16 x 128)
            int srow = idx >> 4, c4 = idx & 15;
            int grow = bm0 + p * 16 + srow;
            const float4* sp = (const float4*)(stg + srow * STGW + c4 * 8);
            uint4 v = pack8h(sp[0], sp[1]);
            int gcol = bn0 + c4 * 8;
            if (gcol < halfN)
                *((uint4*)(YH + (size_t)grow * halfN) + (gcol >> 3)) = v;
            else
                *((uint4*)(ZH + (size_t)grow * halfN) + ((gcol - halfN) >> 3)) = v;
        }
        if (p < 3) __syncthreads();
    }
}

// ---------------- fused aggregate + combine (fp16 y gather + fp16 z) ---------
template <int HL, bool RELU>
__global__ void agg_combine(const uint4* __restrict__ yh4,
                            const uint4* __restrict__ zh4,
                            const int* __restrict__ csrc,
                            const int* __restrict__ offs,
                            const float* __restrict__ b,
                            uint4* __restrict__ outh,
                            float4* __restrict__ outf) {
    int gid = blockIdx.x * blockDim.x + threadIdx.x;
    int node = gid / HL;
    int lane = gid % HL;
    if (RELU) {
        if (node >= NN_PAD) return;
        if (node >= NN) {
            outh[(size_t)node * HL + lane] = make_uint4(0u, 0u, 0u, 0u);
            return;
        }
    } else {
        if (node >= NN) return;
    }

    int s = offs[node], e = offs[node + 1];
    float a[8] = {0.f, 0.f, 0.f, 0.f, 0.f, 0.f, 0.f, 0.f};
    int i = s;
    for (; i + 1 < e; i += 2) {
        uint4 u0 = yh4[(size_t)csrc[i] * HL + lane];
        uint4 u1 = yh4[(size_t)csrc[i + 1] * HL + lane];
        const __half2* p0 = (const __half2*)&u0;
        const __half2* p1 = (const __half2*)&u1;
        #pragma unroll
        for (int k = 0; k < 4; k++) {
            float2 f0 = __half22float2(p0[k]);
            float2 f1 = __half22float2(p1[k]);
            a[2 * k]     += f0.x + f1.x;
            a[2 * k + 1] += f0.y + f1.y;
        }
    }
    if (i < e) {
        uint4 u = yh4[(size_t)csrc[i] * HL + lane];
        const __half2* p = (const __half2*)&u;
        #pragma unroll
        for (int k = 0; k < 4; k++) {
            float2 f = __half22float2(p[k]);
            a[2 * k]     += f.x;
            a[2 * k + 1] += f.y;
        }
    }

    float inv = 1.0f / (float)max(e - s, 1);
    uint4 uz = zh4[(size_t)node * HL + lane];
    const __half2* pz = (const __half2*)&uz;
    float2 zv[4];
    #pragma unroll
    for (int k = 0; k < 4; k++) zv[k] = __half22float2(pz[k]);
    float4 bb0 = ((const float4*)b)[lane * 2 + 0];
    float4 bb1 = ((const float4*)b)[lane * 2 + 1];
    float4 o0, o1;
    o0.x = a[0] * inv + zv[0].x + bb0.x;
    o0.y = a[1] * inv + zv[0].y + bb0.y;
    o0.z = a[2] * inv + zv[1].x + bb0.z;
    o0.w = a[3] * inv + zv[1].y + bb0.w;
    o1.x = a[4] * inv + zv[2].x + bb1.x;
    o1.y = a[5] * inv + zv[2].y + bb1.y;
    o1.z = a[6] * inv + zv[3].x + bb1.z;
    o1.w = a[7] * inv + zv[3].y + bb1.w;
    if (RELU) {
        o0.x = fmaxf(o0.x, 0.f); o0.y = fmaxf(o0.y, 0.f);
        o0.z = fmaxf(o0.z, 0.f); o0.w = fmaxf(o0.w, 0.f);
        o1.x = fmaxf(o1.x, 0.f); o1.y = fmaxf(o1.y, 0.f);
        o1.z = fmaxf(o1.z, 0.f); o1.w = fmaxf(o1.w, 0.f);
        outh[(size_t)node * HL + lane] = pack8h(o0, o1);
    } else {
        outf[(size_t)node * 2 * HL + lane * 2 + 0] = o0;
        outf[(size_t)node * 2 * HL + lane * 2 + 1] = o1;
    }
}

// ---------------------------------------------------------------------------
extern "C" void kernel_launch(void* const* d_in, const int* in_sizes, int n_in,
                              void* d_out, int out_size) {
    const float* x   = (const float*)d_in[0];
    const int*   ei  = (const int*)d_in[1];
    const float* Wl0 = (const float*)d_in[2];
    const float* Wr0 = (const float*)d_in[3];
    const float* b0  = (const float*)d_in[4];
    const float* Wl1 = (const float*)d_in[5];
    const float* Wr1 = (const float*)d_in[6];
    const float* b1  = (const float*)d_in[7];
    const float* Wl2 = (const float*)d_in[8];
    const float* Wr2 = (const float*)d_in[9];
    const float* b2  = (const float*)d_in[10];
    float* out = (float*)d_out;

    const int* src = ei;
    const int* dst = ei + NE;

    __half *xh, *yh, *zh, *h, *wc;
    int *cnt, *offs, *cursor, *csrc, *bsum;
    cudaGetSymbolAddress((void**)&xh,     g_x);
    cudaGetSymbolAddress((void**)&yh,     g_yh);
    cudaGetSymbolAddress((void**)&zh,     g_zh);
    cudaGetSymbolAddress((void**)&h,      g_h);
    cudaGetSymbolAddress((void**)&wc,     g_wcat);
    cudaGetSymbolAddress((void**)&cnt,    g_cnt);
    cudaGetSymbolAddress((void**)&offs,   g_offs);
    cudaGetSymbolAddress((void**)&cursor, g_cursor);
    cudaGetSymbolAddress((void**)&csrc,   g_csrc);
    cudaGetSymbolAddress((void**)&bsum,   g_bsum);
    __half* wc0 = wc;
    __half* wc1 = wc + 256 * 128;
    __half* wc2 = wc + 2 * 256 * 128;

    const int T = 256;
    const int TG = 128;                 // GEMM block size
    dim3 gM(2, NN_PAD / 64);            // N = 256
    dim3 gM1(1, NN_PAD / 64);           // N = 128

    // Fork/join side stream (verified pattern).
    cudaStream_t s2;
    cudaEvent_t evFork, evJoin;
    cudaStreamCreateWithFlags(&s2, cudaStreamNonBlocking);
    cudaEventCreateWithFlags(&evFork, cudaEventDisableTiming);
    cudaEventCreateWithFlags(&evJoin, cudaEventDisableTiming);

    cudaEventRecord(evFork, 0);
    cudaStreamWaitEvent(s2, evFork, 0);

    // ---- main: fp16 prep + layer-0 GEMM (4th kernel launch for ncu) ----
    cvt_x_h<<<(NN_PAD * 16 + T - 1) / T, T>>>((const float4*)x, (uint4*)xh); // 1
    cvt_w_h<<<(2 * 2048 + T - 1) / T, T>>>((const float4*)Wl0,
                                           (const float4*)Wr0,
                                           (uint4*)wc0, 2048);               // 2
    zero_cnt<<<(NN + T - 1) / T, T, 0, s2>>>(cnt);                           // 3 (s2)
    h16gemm_hh<<<gM, TG>>>(xh, wc0, yh, zh, 256);                            // 4 <- ncu

    // ---- side stream: CSR build + remaining weight conversions ----
    count_deg<<<(NE + T - 1) / T, T, 0, s2>>>(dst, cnt);
    scan_a<<<NBLK, SCAN_B, 0, s2>>>(cnt, offs, bsum);
    scan_b<<<1, 128, 0, s2>>>(bsum);
    scan_c<<<(NN + T - 1) / T, T, 0, s2>>>(offs, bsum, cursor);
    place_edges<<<(NE + T - 1) / T, T, 0, s2>>>(src, dst, cursor, csrc);
    cvt_w_h<<<(2 * 2048 + T - 1) / T, T, 0, s2>>>((const float4*)Wl1,
                                                  (const float4*)Wr1,
                                                  (uint4*)wc1, 2048);
    cvt_w_h<<<(2 * 1024 + T - 1) / T, T, 0, s2>>>((const float4*)Wl2,
                                                  (const float4*)Wr2,
                                                  (uint4*)wc2, 1024);
    cudaEventRecord(evJoin, s2);
    cudaStreamWaitEvent(0, evJoin, 0);

    // ---- layer 0 combine (writes fp16 h) ----
    agg_combine<16, true><<<(NN_PAD * 16 + T - 1) / T, T>>>(
        (const uint4*)yh, (const uint4*)zh, csrc, offs, b0, (uint4*)h, nullptr);

    // ---- layer 1 ----
    h16gemm_hh<<<gM, TG>>>(h, wc1, yh, zh, 256);
    agg_combine<16, true><<<(NN_PAD * 16 + T - 1) / T, T>>>(
        (const uint4*)yh, (const uint4*)zh, csrc, offs, b1, (uint4*)h, nullptr);

    // ---- layer 2 (d_out = 64, no relu, fp32 out) ----
    h16gemm_hh<<<gM1, TG>>>(h, wc2, yh, zh, 128);
    agg_combine<8, false><<<(NN * 8 + T - 1) / T, T>>>(
        (const uint4*)yh, (const uint4*)zh, csrc, offs, b2, nullptr, (float4*)out);
}